// round 16
// baseline (speedup 1.0000x reference)
#include <cuda_runtime.h>
#include <cuda_bf16.h>
#include <math.h>

#define FEAT   19
#define NANCH  9
#define P_TOT  (FEAT*FEAT*NANCH)   // 3249
#define P_PAD  3264
#define NCLS   21
#define NOBJ   12
#define B_MAX  256
#define NT     512
#define TA     256
#define NBLK_T ((P_TOT + TA - 1) / TA)   // 13 tiles
#define LCAP   2048
#define NREG   7                    // ceil(P_TOT / NT)

__device__ float g_ll[B_MAX];
__device__ float g_lc[B_MAX];
__device__ float g_np[B_MAX];
__device__ float g_lse  [B_MAX * P_PAD];
__device__ float g_negce[B_MAX * P_PAD];
__device__ unsigned char g_cf[B_MAX * P_PAD];   // pre-patch conf_t (from match kernel)
__device__ unsigned char g_bt[B_MAX * P_PAD];
__device__ unsigned long long g_bp[B_MAX * NOBJ];   // zero-init; B resets after use
__device__ unsigned g_done;                          // zero-init; last block resets

// ---------- kernel 1: matching only (full chip, early-out) ----------
__global__ __launch_bounds__(TA)
void match_kernel(const float* __restrict__ priors,
                  const float* __restrict__ targets)
{
    __shared__ float sT[NOBJ][4];
    __shared__ float sTA_[NOBJ];
    __shared__ int   sLab[NOBJ];
    __shared__ unsigned long long sRed[TA/32][NOBJ];

    const int b    = blockIdx.y;
    const int p0   = blockIdx.x * TA;
    const int np   = min(TA, P_TOT - p0);
    const int tid  = threadIdx.x;
    const int lane = tid & 31, w = tid >> 5;

    const float* tg = targets + (size_t)b * NOBJ * 5;
    if (tid < NOBJ) {
        float x1 = tg[tid*5+0], y1 = tg[tid*5+1];
        float x2 = tg[tid*5+2], y2 = tg[tid*5+3];
        sT[tid][0]=x1; sT[tid][1]=y1; sT[tid][2]=x2; sT[tid][3]=y2;
        sTA_[tid] = __fmul_rn(__fsub_rn(x2, x1), __fsub_rn(y2, y1));
        sLab[tid] = (int)tg[tid*5+4];
    }
    __syncthreads();

    const int  p     = p0 + tid;
    const bool valid = tid < np;
    float px1=0, py1=0, px2=0, py2=0, ap=0;
    if (valid) {
        float4 pr = __ldg((const float4*)priors + p);
        float hw = __fmul_rn(0.5f, pr.z);
        float hh = __fmul_rn(0.5f, pr.w);
        px1 = __fsub_rn(pr.x, hw); py1 = __fsub_rn(pr.y, hh);
        px2 = __fadd_rn(pr.x, hw); py2 = __fadd_rn(pr.y, hh);
        ap  = __fmul_rn(__fsub_rn(px2, px1), __fsub_rn(py2, py1));
    }
    float best = -1.0f; int bt = 0;

    #pragma unroll
    for (int t = 0; t < NOBJ; t++) {
        unsigned ovbits = 0u;
        if (valid) {
            float iw = __fsub_rn(fminf(sT[t][2], px2), fmaxf(sT[t][0], px1));
            float ih = __fsub_rn(fminf(sT[t][3], py2), fmaxf(sT[t][1], py1));
            iw = fmaxf(iw, 0.0f); ih = fmaxf(ih, 0.0f);
            float inter = __fmul_rn(iw, ih);
            if (inter > 0.0f) {
                float uni = __fsub_rn(__fadd_rn(sTA_[t], ap), inter);
                float ov  = __fdiv_rn(inter, uni);
                if (ov > best) { best = ov; bt = t; }   // first-max over t
                ovbits = __float_as_uint(ov);
            } else {
                // inter == 0 -> ov == 0 exactly; beats best only when best < 0
                if (0.0f > best) { best = 0.0f; bt = t; }
            }
        }
        unsigned mx    = __reduce_max_sync(0xFFFFFFFFu, ovbits);
        unsigned peers = __ballot_sync(0xFFFFFFFFu, valid && (ovbits == mx));
        if (peers) {
            if (lane == __ffs(peers) - 1)               // lowest lane = smallest p
                sRed[w][t] = (((unsigned long long)mx) << 32)
                           | (unsigned)(0xFFFFFFFFu - (unsigned)p);
        } else if (lane == 0) sRed[w][t] = 0ULL;
    }

    if (valid) {
        size_t o = (size_t)b * P_PAD + p;
        int cf = (best < 0.5f) ? 0 : (sLab[bt] + 1);
        g_cf[o] = (unsigned char)cf;
        g_bt[o] = (unsigned char)bt;
    }
    __syncthreads();
    if (tid < NOBJ) {
        unsigned long long mm = 0ULL;
        #pragma unroll
        for (int ww = 0; ww < TA/32; ww++)
            if (sRed[ww][tid] > mm) mm = sRed[ww][tid];
        if (mm) atomicMax(&g_bp[b * NOBJ + tid], mm);
    }
}

// ---------- kernel 2: pure coalesced logsumexp streamer (measured 19.4us) ----------
__global__ __launch_bounds__(TA)
void lse_kernel(const float* __restrict__ conf)
{
    __shared__ float s[TA * NCLS];   // 21504 B
    const int b  = blockIdx.y;
    const int p0 = blockIdx.x * TA;
    const int np = min(TA, P_TOT - p0);
    const int tot = np * NCLS;
    const size_t st = ((size_t)b * P_TOT + p0) * NCLS;
    const float* gp = conf + st;
    const int tid = threadIdx.x;

    int head = (int)((4 - (st & 3)) & 3); if (head > tot) head = tot;
    for (int i = tid; i < head; i += TA) s[i] = gp[i];
    int nb4 = (tot - head) >> 2;
    const float4* g4 = (const float4*)(gp + head);
    for (int i = tid; i < nb4; i += TA) {
        float4 v = g4[i]; int o = head + 4*i;
        s[o] = v.x; s[o+1] = v.y; s[o+2] = v.z; s[o+3] = v.w;
    }
    for (int i = head + 4*nb4 + tid; i < tot; i += TA) s[i] = gp[i];
    __syncthreads();

    if (tid < np) {
        const float* x = s + tid * NCLS;
        float m = x[0];
        #pragma unroll
        for (int i = 1; i < NCLS; i++) m = fmaxf(m, x[i]);
        float sum = 0.0f;
        #pragma unroll
        for (int i = 0; i < NCLS; i++) sum += __expf(x[i] - m);
        float lse = m + __logf(sum);
        size_t o = (size_t)b * P_PAD + p0 + tid;
        g_lse  [o] = lse;
        g_negce[o] = __fsub_rn(lse, x[0]);
    }
}

// block-wide sum over NT=512 threads
__device__ __forceinline__ float blkSum(float v, float* sW) {
    int tid = threadIdx.x;
    #pragma unroll
    for (int o = 16; o > 0; o >>= 1) v += __shfl_down_sync(0xFFFFFFFFu, v, o);
    if ((tid & 31) == 0) sW[tid >> 5] = v;
    __syncthreads();
    if (tid < 32) {
        float w = (tid < NT / 32) ? sW[tid] : 0.0f;
        #pragma unroll
        for (int o = 8; o > 0; o >>= 1) w += __shfl_down_sync(0xFFFFFFFFu, w, o);
        if (tid == 0) sW[0] = w;
    }
    __syncthreads();
    float r = sW[0];
    __syncthreads();
    return r;
}

__device__ __forceinline__ void blkSum3(float& a, float& b, float& c, float* sW) {
    int tid = threadIdx.x;
    #pragma unroll
    for (int o = 16; o > 0; o >>= 1) {
        a += __shfl_down_sync(0xFFFFFFFFu, a, o);
        b += __shfl_down_sync(0xFFFFFFFFu, b, o);
        c += __shfl_down_sync(0xFFFFFFFFu, c, o);
    }
    if ((tid & 31) == 0) { int w = tid >> 5; sW[w] = a; sW[16+w] = b; sW[32+w] = c; }
    __syncthreads();
    if (tid < 16) {
        float x = sW[tid], y = sW[16+tid], z = sW[32+tid];
        #pragma unroll
        for (int o = 8; o > 0; o >>= 1) {
            x += __shfl_down_sync(0x0000FFFFu, x, o);
            y += __shfl_down_sync(0x0000FFFFu, y, o);
            z += __shfl_down_sync(0x0000FFFFu, z, o);
        }
        if (tid == 0) { sW[0] = x; sW[1] = y; sW[2] = z; }
    }
    __syncthreads();
    a = sW[0]; b = sW[1]; c = sW[2];
    __syncthreads();
}

// ---------- kernel 3: per-batch select / losses / featuremaps ----------
__global__ __launch_bounds__(NT)
void multibox_loss_kernel(const float* __restrict__ loc,
                          const float* __restrict__ conf,
                          const float* __restrict__ priors,
                          const float* __restrict__ targets,
                          float* __restrict__ out, int B)
{
    __shared__ float sVal[P_TOT];
    __shared__ unsigned char sCf[P_TOT];
    __shared__ unsigned char sBt[P_TOT];
    __shared__ unsigned char sSel[P_TOT];
    __shared__ unsigned long long sBuf[LCAP];   // hist int[4096] ∪ list u64[2048]
    __shared__ float sT[NOBJ][4];
    __shared__ int   sLab[NOBJ];
    __shared__ int   sFp[NOBJ];
    __shared__ float sW[48];
    __shared__ int   sWarpTot[16];
    __shared__ int   sDig[2];
    __shared__ int   sCnt;
    __shared__ int   sLast;

    int* hist = (int*)sBuf;

    const int b    = blockIdx.x;
    const int tid  = threadIdx.x;
    const int lane = tid & 31;

    const float* tg = targets + (size_t)b * NOBJ * 5;
    if (tid < NOBJ) {
        sT[tid][0]=tg[tid*5+0]; sT[tid][1]=tg[tid*5+1];
        sT[tid][2]=tg[tid*5+2]; sT[tid][3]=tg[tid*5+3];
        sLab[tid] = (int)tg[tid*5+4];
        unsigned long long bp = g_bp[b * NOBJ + tid];
        g_bp[b * NOBJ + tid] = 0ULL;            // reset for next graph replay
        sFp[tid] = (int)(0xFFFFFFFFu - (unsigned)(bp & 0xFFFFFFFFull));
    }
    for (int i = tid; i < 4096; i += NT) hist[i] = 0;
    __syncthreads();

    // ---- fused load pass: cf/bt/negce -> regs+smem ----
    const size_t bo = (size_t)b * P_PAD;
    float negr[NREG];
    {
        int i = 0;
        for (int p = tid; p < P_TOT; p += NT, i++) {
            sCf[p]  = g_cf[bo + p];
            sBt[p]  = g_bt[bo + p];
            negr[i] = g_negce[bo + p];
        }
    }
    __syncthreads();

    // forced match: serial last-wins patch
    if (tid == 0) {
        for (int t = 0; t < NOBJ; t++) {
            int p = sFp[t];
            sCf[p] = (unsigned char)(sLab[t] + 1);
            sBt[p] = (unsigned char)t;
        }
        sCnt = 0;
    }
    __syncthreads();

    // ---- phase 2: val + hist + CE + loc loss (register-fed) ----
    float lossl = 0.0f, posce = 0.0f, npos = 0.0f;
    {
        int i = 0;
        for (int p = tid; p < P_TOT; p += NT, i++) {
            int cf = sCf[p];
            float val;
            if (cf > 0) {
                val = 0.0f;
                int t = sBt[p];
                float lse = __ldg(&g_lse[bo + p]);
                float g   = __ldg(conf + ((size_t)b * P_TOT + p) * NCLS + cf);
                npos  += 1.0f;
                posce += lse - g;
                float4 ld = __ldg((const float4*)loc + (size_t)b * P_TOT + p);
                float4 pr = __ldg((const float4*)priors + p);
                float tx1 = sT[t][0], ty1 = sT[t][1], tx2 = sT[t][2], ty2 = sT[t][3];
                float e0 = ((tx1 + tx2) * 0.5f - pr.x) / (0.1f * pr.z);
                float e1 = ((ty1 + ty2) * 0.5f - pr.y) / (0.1f * pr.w);
                float e2 = logf((tx2 - tx1) / pr.z) * 5.0f;
                float e3 = logf((ty2 - ty1) / pr.w) * 5.0f;
                float d, ad;
                d = ld.x - e0; ad = fabsf(d); lossl += (ad < 1.0f) ? 0.5f*d*d : ad - 0.5f;
                d = ld.y - e1; ad = fabsf(d); lossl += (ad < 1.0f) ? 0.5f*d*d : ad - 0.5f;
                d = ld.z - e2; ad = fabsf(d); lossl += (ad < 1.0f) ? 0.5f*d*d : ad - 0.5f;
                d = ld.w - e3; ad = fabsf(d); lossl += (ad < 1.0f) ? 0.5f*d*d : ad - 0.5f;
            } else {
                val = negr[i];
            }
            sVal[p] = val;
            atomicAdd(&hist[__float_as_uint(val) >> 19], 1);
        }
    }
    __syncthreads();

    float npos_t = npos, posce_t = posce, lossl_t = lossl;
    blkSum3(npos_t, posce_t, lossl_t, sW);
    int k = min(3 * (int)npos_t, P_TOT - 1);

    // ---- threshold bin via suffix scan over 4096 bins ----
    {
        const int w = tid >> 5;
        int h8[8]; int s = 0;
        int lo = tid * 8;
        #pragma unroll
        for (int i = 0; i < 8; i++) { h8[i] = hist[lo + i]; s += h8[i]; }
        int suf = s;
        #pragma unroll
        for (int off = 1; off < 32; off <<= 1) {
            int t2 = __shfl_down_sync(0xFFFFFFFFu, suf, off);
            if (lane + off < 32) suf += t2;
        }
        if (lane == 0) sWarpTot[w] = suf;
        __syncthreads();
        int W = 0;
        for (int ww = w + 1; ww < 16; ww++) W += sWarpTot[ww];
        int cgt = W + (suf - s);
        #pragma unroll
        for (int i = 7; i >= 0; i--) {
            int c = h8[i];
            if (cgt < k && k <= cgt + c) { sDig[0] = lo + i; sDig[1] = k - cgt; }
            cgt += c;
        }
        __syncthreads();
    }
    const int T  = sDig[0];
    const int kk = sDig[1];

    // ---- classify pass (hist memory becomes the list) ----
    unsigned long long* list = sBuf;
    float negsum = 0.0f;
    for (int p = tid; p < P_TOT; p += NT) {
        int pos = sCf[p] > 0;
        unsigned u = __float_as_uint(sVal[p]);
        int bin = (int)(u >> 19);
        int sel = pos;
        if (bin > T) {
            sel = 1;
            if (!pos) negsum += sVal[p];
        } else if (bin == T) {
            int idx = atomicAdd(&sCnt, 1);
            if (idx < LCAP)
                list[idx] = (((unsigned long long)u) << 32)
                          | (unsigned)(0xFFFFFFFFu - (unsigned)p);
        }
        sSel[p] = (unsigned char)sel;
    }
    __syncthreads();

    // ---- exact rank inside threshold bin (value desc, index asc) ----
    const int cnt = min(sCnt, LCAP);
    for (int i = tid; i < cnt; i += NT) {
        unsigned long long me = list[i];
        int r = 0;
        for (int j = 0; j < cnt; j++) r += (list[j] > me) ? 1 : 0;
        if (r < kk) {
            int p = (int)(0xFFFFFFFFu - (unsigned)(me & 0xFFFFFFFFull));
            sSel[p] = 1;
            if (sCf[p] == 0) negsum += __uint_as_float((unsigned)(me >> 32));
        }
    }
    float lossc_t = posce_t + blkSum(negsum, sW);

    // ---- featuremaps ----
    for (int c = tid; c < FEAT * FEAT; c += NT) {
        int base = c * NANCH;
        int mc = 0, ms = 0;
        #pragma unroll
        for (int a = 0; a < NANCH; a++) {
            mc = max(mc, (int)sCf[base + a]);
            ms = max(ms, (int)sSel[base + a]);
        }
        out[2 + (size_t)b * (FEAT*FEAT) + c]                           = (float)mc;
        out[2 + (size_t)B * (FEAT*FEAT) + (size_t)b * (FEAT*FEAT) + c] = (float)ms;
    }

    // ---- fused finalize ----
    if (tid == 0) {
        g_ll[b] = lossl_t;
        g_lc[b] = lossc_t;
        g_np[b] = npos_t;
        __threadfence();
        unsigned t = atomicAdd(&g_done, 1u);
        sLast = (t == (unsigned)(B - 1));
    }
    __syncthreads();
    if (sLast) {
        __threadfence();
        float ll = (tid < B) ? __ldcg(&g_ll[tid]) : 0.0f;
        float lc = (tid < B) ? __ldcg(&g_lc[tid]) : 0.0f;
        float nn = (tid < B) ? __ldcg(&g_np[tid]) : 0.0f;
        blkSum3(ll, lc, nn, sW);
        if (tid == 0) {
            out[0] = ll / nn;
            out[1] = lc / nn;
            g_done = 0;
        }
    }
}

extern "C" void kernel_launch(void* const* d_in, const int* in_sizes, int n_in,
                              void* d_out, int out_size)
{
    const float* loc     = (const float*)d_in[0];
    const float* conf    = (const float*)d_in[1];
    const float* priors  = (const float*)d_in[2];
    const float* targets = (const float*)d_in[3];
    float* out = (float*)d_out;

    int B = in_sizes[3] / (NOBJ * 5);   // 256

    dim3 gT(NBLK_T, B);
    match_kernel<<<gT, TA>>>(priors, targets);
    lse_kernel<<<gT, TA>>>(conf);
    multibox_loss_kernel<<<B, NT>>>(loc, conf, priors, targets, out, B);
}

// round 17
// speedup vs baseline: 1.1341x; 1.1341x over previous
#include <cuda_runtime.h>
#include <cuda_bf16.h>
#include <math.h>

#define FEAT   19
#define NANCH  9
#define P_TOT  (FEAT*FEAT*NANCH)   // 3249
#define P_PAD  3264
#define NCLS   21
#define NOBJ   12
#define B_MAX  256
#define NT     512
#define TA     256
#define NBLK_T ((P_TOT + TA - 1) / TA)   // 13 tiles
#define LCAP   2048
#define NREG   7                    // ceil(P_TOT / NT)

__device__ float g_ll[B_MAX];
__device__ float g_lc[B_MAX];
__device__ float g_np[B_MAX];
__device__ float g_lse  [B_MAX * P_PAD];
__device__ float g_negce[B_MAX * P_PAD];
__device__ unsigned char g_cf[B_MAX * P_PAD];   // pre-patch conf_t
__device__ unsigned char g_bt[B_MAX * P_PAD];
__device__ unsigned long long g_bp[B_MAX * NOBJ];   // zero-init; B resets after use
__device__ unsigned g_done;                          // zero-init; last block resets

// --------- kernel A: grid (26, B). x<13: lse tile. x>=13: match tile. ---------
__global__ __launch_bounds__(TA)
void prep_kernel(const float* __restrict__ conf,
                 const float* __restrict__ priors,
                 const float* __restrict__ targets)
{
    const int b   = blockIdx.y;
    const int tid = threadIdx.x;

    if (blockIdx.x < NBLK_T) {
        // ---------------- lse tile (proven streaming shape) ----------------
        __shared__ float s[TA * NCLS];   // 21504 B
        const int p0 = blockIdx.x * TA;
        const int np = min(TA, P_TOT - p0);
        const int tot = np * NCLS;
        const size_t st = ((size_t)b * P_TOT + p0) * NCLS;
        const float* gp = conf + st;

        int head = (int)((4 - (st & 3)) & 3); if (head > tot) head = tot;
        for (int i = tid; i < head; i += TA) s[i] = gp[i];
        int nb4 = (tot - head) >> 2;
        const float4* g4 = (const float4*)(gp + head);
        for (int i = tid; i < nb4; i += TA) {
            float4 v = g4[i]; int o = head + 4*i;
            s[o] = v.x; s[o+1] = v.y; s[o+2] = v.z; s[o+3] = v.w;
        }
        for (int i = head + 4*nb4 + tid; i < tot; i += TA) s[i] = gp[i];
        __syncthreads();

        if (tid < np) {
            const float* x = s + tid * NCLS;
            float m = x[0];
            #pragma unroll
            for (int i = 1; i < NCLS; i++) m = fmaxf(m, x[i]);
            float sum = 0.0f;
            #pragma unroll
            for (int i = 0; i < NCLS; i++) sum += __expf(x[i] - m);
            float lse = m + __logf(sum);
            size_t o = (size_t)b * P_PAD + p0 + tid;
            g_lse  [o] = lse;
            g_negce[o] = __fsub_rn(lse, x[0]);
        }
    } else {
        // ---- match tile: float4 truths, early-out, ballot-skip reduction ----
        __shared__ float4 sT4[NOBJ];
        __shared__ float  sTA_[NOBJ];
        __shared__ int    sLab[NOBJ];
        __shared__ unsigned long long sRed[TA/32][NOBJ];

        const int p0 = (blockIdx.x - NBLK_T) * TA;
        const int np = min(TA, P_TOT - p0);
        const int lane = tid & 31, w = tid >> 5;

        const float* tg = targets + (size_t)b * NOBJ * 5;
        if (tid < NOBJ) {
            float x1 = tg[tid*5+0], y1 = tg[tid*5+1];
            float x2 = tg[tid*5+2], y2 = tg[tid*5+3];
            sT4[tid] = make_float4(x1, y1, x2, y2);
            sTA_[tid] = __fmul_rn(__fsub_rn(x2, x1), __fsub_rn(y2, y1));
            sLab[tid] = (int)tg[tid*5+4];
        }
        __syncthreads();

        const int  p     = p0 + tid;
        const bool valid = tid < np;
        const unsigned vmask = __ballot_sync(0xFFFFFFFFu, valid);
        const int vlead = __ffs(vmask) - 1;   // lowest valid lane (-1 if none)
        float px1=0, py1=0, px2=0, py2=0, ap=0;
        if (valid) {
            float4 pr = __ldg((const float4*)priors + p);
            float hw = __fmul_rn(0.5f, pr.z);
            float hh = __fmul_rn(0.5f, pr.w);
            px1 = __fsub_rn(pr.x, hw); py1 = __fsub_rn(pr.y, hh);
            px2 = __fadd_rn(pr.x, hw); py2 = __fadd_rn(pr.y, hh);
            ap  = __fmul_rn(__fsub_rn(px2, px1), __fsub_rn(py2, py1));
        }
        float best = -1.0f; int bt = 0;

        #pragma unroll
        for (int t = 0; t < NOBJ; t++) {
            unsigned ovbits = 0u;
            if (valid) {
                float4 tt = sT4[t];
                float iw = __fsub_rn(fminf(tt.z, px2), fmaxf(tt.x, px1));
                float ih = __fsub_rn(fminf(tt.w, py2), fmaxf(tt.y, py1));
                iw = fmaxf(iw, 0.0f); ih = fmaxf(ih, 0.0f);
                float inter = __fmul_rn(iw, ih);
                if (inter > 0.0f) {
                    float uni = __fsub_rn(__fadd_rn(sTA_[t], ap), inter);
                    float ov  = __fdiv_rn(inter, uni);
                    if (ov > best) { best = ov; bt = t; }   // first-max over t
                    ovbits = __float_as_uint(ov);           // > 0
                } else {
                    // inter == 0 -> ov == 0 exactly; beats best only when best < 0
                    if (0.0f > best) { best = 0.0f; bt = t; }
                }
            }
            unsigned nz = __ballot_sync(0xFFFFFFFFu, ovbits != 0u);
            if (nz) {
                unsigned mx = __reduce_max_sync(0xFFFFFFFFu, ovbits);
                unsigned peers = __ballot_sync(0xFFFFFFFFu, ovbits == mx);
                if (lane == __ffs(peers) - 1)               // lowest lane = smallest p
                    sRed[w][t] = (((unsigned long long)mx) << 32)
                               | (unsigned)(0xFFFFFFFFu - (unsigned)p);
            } else {
                // all-zero overlap in this warp: candidate (0, smallest valid p)
                if (lane == vlead)
                    sRed[w][t] = (unsigned long long)
                                 (unsigned)(0xFFFFFFFFu - (unsigned)p);
                else if (vmask == 0u && lane == 0)
                    sRed[w][t] = 0ULL;
            }
        }

        if (valid) {
            size_t o = (size_t)b * P_PAD + p;
            int cf = (best < 0.5f) ? 0 : (sLab[bt] + 1);
            g_cf[o] = (unsigned char)cf;
            g_bt[o] = (unsigned char)bt;
        }
        __syncthreads();
        if (tid < NOBJ) {
            unsigned long long mm = 0ULL;
            #pragma unroll
            for (int ww = 0; ww < TA/32; ww++)
                if (sRed[ww][tid] > mm) mm = sRed[ww][tid];
            if (mm) atomicMax(&g_bp[b * NOBJ + tid], mm);
        }
    }
}

// block-wide sum over NT=512 threads
__device__ __forceinline__ float blkSum(float v, float* sW) {
    int tid = threadIdx.x;
    #pragma unroll
    for (int o = 16; o > 0; o >>= 1) v += __shfl_down_sync(0xFFFFFFFFu, v, o);
    if ((tid & 31) == 0) sW[tid >> 5] = v;
    __syncthreads();
    if (tid < 32) {
        float w = (tid < NT / 32) ? sW[tid] : 0.0f;
        #pragma unroll
        for (int o = 8; o > 0; o >>= 1) w += __shfl_down_sync(0xFFFFFFFFu, w, o);
        if (tid == 0) sW[0] = w;
    }
    __syncthreads();
    float r = sW[0];
    __syncthreads();
    return r;
}

__device__ __forceinline__ void blkSum3(float& a, float& b, float& c, float* sW) {
    int tid = threadIdx.x;
    #pragma unroll
    for (int o = 16; o > 0; o >>= 1) {
        a += __shfl_down_sync(0xFFFFFFFFu, a, o);
        b += __shfl_down_sync(0xFFFFFFFFu, b, o);
        c += __shfl_down_sync(0xFFFFFFFFu, c, o);
    }
    if ((tid & 31) == 0) { int w = tid >> 5; sW[w] = a; sW[16+w] = b; sW[32+w] = c; }
    __syncthreads();
    if (tid < 16) {
        float x = sW[tid], y = sW[16+tid], z = sW[32+tid];
        #pragma unroll
        for (int o = 8; o > 0; o >>= 1) {
            x += __shfl_down_sync(0x0000FFFFu, x, o);
            y += __shfl_down_sync(0x0000FFFFu, y, o);
            z += __shfl_down_sync(0x0000FFFFu, z, o);
        }
        if (tid == 0) { sW[0] = x; sW[1] = y; sW[2] = z; }
    }
    __syncthreads();
    a = sW[0]; b = sW[1]; c = sW[2];
    __syncthreads();
}

// ------------- kernel B: per-batch select / losses / featuremaps ----------
__global__ __launch_bounds__(NT)
void multibox_loss_kernel(const float* __restrict__ loc,
                          const float* __restrict__ conf,
                          const float* __restrict__ priors,
                          const float* __restrict__ targets,
                          float* __restrict__ out, int B)
{
    __shared__ float sVal[P_TOT];
    __shared__ unsigned char sCf[P_TOT];
    __shared__ unsigned char sBt[P_TOT];
    __shared__ unsigned char sSel[P_TOT];
    __shared__ unsigned long long sBuf[LCAP];   // hist int[4096] ∪ list u64[2048]
    __shared__ float sT[NOBJ][4];
    __shared__ int   sLab[NOBJ];
    __shared__ int   sFp[NOBJ];
    __shared__ float sW[48];
    __shared__ int   sWarpTot[16];
    __shared__ int   sDig[2];
    __shared__ int   sCnt;
    __shared__ int   sLast;

    int* hist = (int*)sBuf;

    const int b    = blockIdx.x;
    const int tid  = threadIdx.x;
    const int lane = tid & 31;

    const float* tg = targets + (size_t)b * NOBJ * 5;
    if (tid < NOBJ) {
        sT[tid][0]=tg[tid*5+0]; sT[tid][1]=tg[tid*5+1];
        sT[tid][2]=tg[tid*5+2]; sT[tid][3]=tg[tid*5+3];
        sLab[tid] = (int)tg[tid*5+4];
        unsigned long long bp = g_bp[b * NOBJ + tid];
        g_bp[b * NOBJ + tid] = 0ULL;            // reset for next graph replay
        sFp[tid] = (int)(0xFFFFFFFFu - (unsigned)(bp & 0xFFFFFFFFull));
    }
    for (int i = tid; i < 4096; i += NT) hist[i] = 0;
    __syncthreads();

    // ---- fused load pass: cf/bt/negce -> regs+smem ----
    const size_t bo = (size_t)b * P_PAD;
    float negr[NREG];
    {
        int i = 0;
        for (int p = tid; p < P_TOT; p += NT, i++) {
            sCf[p]  = g_cf[bo + p];
            sBt[p]  = g_bt[bo + p];
            negr[i] = g_negce[bo + p];
        }
    }
    __syncthreads();

    // forced match: serial last-wins patch
    if (tid == 0) {
        for (int t = 0; t < NOBJ; t++) {
            int p = sFp[t];
            sCf[p] = (unsigned char)(sLab[t] + 1);
            sBt[p] = (unsigned char)t;
        }
        sCnt = 0;
    }
    __syncthreads();

    // ---- phase 2: val + hist + CE + loc loss (register-fed) ----
    float lossl = 0.0f, posce = 0.0f, npos = 0.0f;
    {
        int i = 0;
        for (int p = tid; p < P_TOT; p += NT, i++) {
            int cf = sCf[p];
            float val;
            if (cf > 0) {
                val = 0.0f;
                int t = sBt[p];
                float lse = __ldg(&g_lse[bo + p]);
                float g   = __ldg(conf + ((size_t)b * P_TOT + p) * NCLS + cf);
                npos  += 1.0f;
                posce += lse - g;
                float4 ld = __ldg((const float4*)loc + (size_t)b * P_TOT + p);
                float4 pr = __ldg((const float4*)priors + p);
                float tx1 = sT[t][0], ty1 = sT[t][1], tx2 = sT[t][2], ty2 = sT[t][3];
                float e0 = ((tx1 + tx2) * 0.5f - pr.x) / (0.1f * pr.z);
                float e1 = ((ty1 + ty2) * 0.5f - pr.y) / (0.1f * pr.w);
                float e2 = logf((tx2 - tx1) / pr.z) * 5.0f;
                float e3 = logf((ty2 - ty1) / pr.w) * 5.0f;
                float d, ad;
                d = ld.x - e0; ad = fabsf(d); lossl += (ad < 1.0f) ? 0.5f*d*d : ad - 0.5f;
                d = ld.y - e1; ad = fabsf(d); lossl += (ad < 1.0f) ? 0.5f*d*d : ad - 0.5f;
                d = ld.z - e2; ad = fabsf(d); lossl += (ad < 1.0f) ? 0.5f*d*d : ad - 0.5f;
                d = ld.w - e3; ad = fabsf(d); lossl += (ad < 1.0f) ? 0.5f*d*d : ad - 0.5f;
            } else {
                val = negr[i];
            }
            sVal[p] = val;
            atomicAdd(&hist[__float_as_uint(val) >> 19], 1);
        }
    }
    __syncthreads();

    float npos_t = npos, posce_t = posce, lossl_t = lossl;
    blkSum3(npos_t, posce_t, lossl_t, sW);
    int k = min(3 * (int)npos_t, P_TOT - 1);

    // ---- threshold bin via suffix scan over 4096 bins ----
    {
        const int w = tid >> 5;
        int h8[8]; int s = 0;
        int lo = tid * 8;
        #pragma unroll
        for (int i = 0; i < 8; i++) { h8[i] = hist[lo + i]; s += h8[i]; }
        int suf = s;
        #pragma unroll
        for (int off = 1; off < 32; off <<= 1) {
            int t2 = __shfl_down_sync(0xFFFFFFFFu, suf, off);
            if (lane + off < 32) suf += t2;
        }
        if (lane == 0) sWarpTot[w] = suf;
        __syncthreads();
        int W = 0;
        for (int ww = w + 1; ww < 16; ww++) W += sWarpTot[ww];
        int cgt = W + (suf - s);
        #pragma unroll
        for (int i = 7; i >= 0; i--) {
            int c = h8[i];
            if (cgt < k && k <= cgt + c) { sDig[0] = lo + i; sDig[1] = k - cgt; }
            cgt += c;
        }
        __syncthreads();
    }
    const int T  = sDig[0];
    const int kk = sDig[1];

    // ---- classify pass (hist memory becomes the list) ----
    unsigned long long* list = sBuf;
    float negsum = 0.0f;
    for (int p = tid; p < P_TOT; p += NT) {
        int pos = sCf[p] > 0;
        unsigned u = __float_as_uint(sVal[p]);
        int bin = (int)(u >> 19);
        int sel = pos;
        if (bin > T) {
            sel = 1;
            if (!pos) negsum += sVal[p];
        } else if (bin == T) {
            int idx = atomicAdd(&sCnt, 1);
            if (idx < LCAP)
                list[idx] = (((unsigned long long)u) << 32)
                          | (unsigned)(0xFFFFFFFFu - (unsigned)p);
        }
        sSel[p] = (unsigned char)sel;
    }
    __syncthreads();

    // ---- exact rank inside threshold bin (value desc, index asc) ----
    const int cnt = min(sCnt, LCAP);
    for (int i = tid; i < cnt; i += NT) {
        unsigned long long me = list[i];
        int r = 0;
        for (int j = 0; j < cnt; j++) r += (list[j] > me) ? 1 : 0;
        if (r < kk) {
            int p = (int)(0xFFFFFFFFu - (unsigned)(me & 0xFFFFFFFFull));
            sSel[p] = 1;
            if (sCf[p] == 0) negsum += __uint_as_float((unsigned)(me >> 32));
        }
    }
    float lossc_t = posce_t + blkSum(negsum, sW);

    // ---- featuremaps ----
    for (int c = tid; c < FEAT * FEAT; c += NT) {
        int base = c * NANCH;
        int mc = 0, ms = 0;
        #pragma unroll
        for (int a = 0; a < NANCH; a++) {
            mc = max(mc, (int)sCf[base + a]);
            ms = max(ms, (int)sSel[base + a]);
        }
        out[2 + (size_t)b * (FEAT*FEAT) + c]                           = (float)mc;
        out[2 + (size_t)B * (FEAT*FEAT) + (size_t)b * (FEAT*FEAT) + c] = (float)ms;
    }

    // ---- fused finalize ----
    if (tid == 0) {
        g_ll[b] = lossl_t;
        g_lc[b] = lossc_t;
        g_np[b] = npos_t;
        __threadfence();
        unsigned t = atomicAdd(&g_done, 1u);
        sLast = (t == (unsigned)(B - 1));
    }
    __syncthreads();
    if (sLast) {
        __threadfence();
        float ll = (tid < B) ? __ldcg(&g_ll[tid]) : 0.0f;
        float lc = (tid < B) ? __ldcg(&g_lc[tid]) : 0.0f;
        float nn = (tid < B) ? __ldcg(&g_np[tid]) : 0.0f;
        blkSum3(ll, lc, nn, sW);
        if (tid == 0) {
            out[0] = ll / nn;
            out[1] = lc / nn;
            g_done = 0;
        }
    }
}

extern "C" void kernel_launch(void* const* d_in, const int* in_sizes, int n_in,
                              void* d_out, int out_size)
{
    const float* loc     = (const float*)d_in[0];
    const float* conf    = (const float*)d_in[1];
    const float* priors  = (const float*)d_in[2];
    const float* targets = (const float*)d_in[3];
    float* out = (float*)d_out;

    int B = in_sizes[3] / (NOBJ * 5);   // 256

    dim3 gA(2 * NBLK_T, B);
    prep_kernel<<<gA, TA>>>(conf, priors, targets);
    multibox_loss_kernel<<<B, NT>>>(loc, conf, priors, targets, out, B);
}